// round 1
// baseline (speedup 1.0000x reference)
#include <cuda_runtime.h>
#include <math.h>
#include <stdint.h>

#define T_STEPS 64
#define NN 16384
#define NE 262144
#define F_IN 8
#define H1 12
#define C1 16
#define HID 192
#define CAP0 256
#define MAX_SLOTS 128
#define CAPE 4096
#define LOCAL_CAP 128
#define NB 32
#define NG 512

// ---------------- scratch (static device globals; no allocation) ----------------
__device__ int   g_cnt0[T_STEPS];
__device__ int   g_e0[T_STEPS][CAP0];
__device__ int   g_s0[T_STEPS][CAP0];
__device__ int   g_scnt[T_STEPS];
__device__ int   g_S[T_STEPS][MAX_SLOTS];
__device__ short g_map[T_STEPS][NN];
__device__ int   g_incnt[T_STEPS];
__device__ int   g_ie_e[T_STEPS][CAPE];
__device__ int   g_ie_src[T_STEPS][CAPE];
__device__ int   g_ie_slot[T_STEPS][CAPE];
__device__ float g_xl2[T_STEPS][MAX_SLOTS];
__device__ float g_series[T_STEPS];
__device__ float4 g_W0T[32 * NG];   // Whh0 packed: [k4][g] -> Whh0[g][4k4..4k4+3]
__device__ float4 g_Wi1T[32 * NG];  // Wih1 packed
__device__ float4 g_Wh1T[32 * NG];  // Whh1 packed

__device__ __forceinline__ float lrelu(float x) { return x > 0.f ? x : 0.2f * x; }

__device__ __forceinline__ void edit_factor(int e, float& mul, float& add) {
    mul = 1.f; add = 0.f;
    if (e >= 0 && e < 23) {
        switch (e) {
            case 1: case 2: case 12: case 17: case 19: case 22: mul = 0.9f; break;
            case 7: case 14: mul = 0.9f; add = 0.1f; break;
            case 10: case 13: mul = 0.9f; add = 0.05f; break;
            default: break;
        }
    }
}

// ---------------- K0: init counters + node->slot map ----------------
__global__ void k_init() {
    int idx = blockIdx.x * blockDim.x + threadIdx.x;
    int stride = gridDim.x * blockDim.x;
    int* mp = (int*)g_map;
    const int nwords = T_STEPS * NN / 2;
    for (int i = idx; i < nwords; i += stride) mp[i] = -1;  // 0xFFFFFFFF = two -1 shorts
    if (idx < T_STEPS) { g_cnt0[idx] = 0; g_scnt[idx] = 0; g_incnt[idx] = 0; }
}

// ---------------- K1: find edges with dst == 0 ----------------
__global__ void k_pass1(const int* __restrict__ ei) {
    int t = blockIdx.y;
    const int* src = ei + (size_t)t * 2 * NE;
    const int* dst = src + NE;
    int per_block = NE / gridDim.x;
    int e0 = blockIdx.x * per_block;
    for (int e = e0 + threadIdx.x * 4; e < e0 + per_block; e += blockDim.x * 4) {
        int4 d = *(const int4*)(dst + e);
        int dd[4] = { d.x, d.y, d.z, d.w };
        #pragma unroll
        for (int k = 0; k < 4; k++) {
            if (dd[k] == 0) {
                int p = atomicAdd(&g_cnt0[t], 1);
                if (p < CAP0) { g_e0[t][p] = e + k; g_s0[t][p] = src[e + k]; }
            }
        }
    }
}

// ---------------- K2: sort node-0 edges, build frontier set S + map ----------------
__global__ void k_build() {
    int t = blockIdx.x;
    if (threadIdx.x != 0) return;
    int n = g_cnt0[t]; if (n > CAP0) n = CAP0;
    g_cnt0[t] = n;
    // insertion sort by global edge index (canonical order -> deterministic sums)
    for (int i = 1; i < n; i++) {
        int ke = g_e0[t][i], ks = g_s0[t][i], j = i - 1;
        while (j >= 0 && g_e0[t][j] > ke) {
            g_e0[t][j + 1] = g_e0[t][j]; g_s0[t][j + 1] = g_s0[t][j]; j--;
        }
        g_e0[t][j + 1] = ke; g_s0[t][j + 1] = ks;
    }
    int sc = 0;
    g_map[t][0] = 0; g_S[t][0] = 0; sc = 1;   // node 0 = slot 0
    for (int i = 0; i < n; i++) {
        int s = g_s0[t][i];
        if (g_map[t][s] < 0 && sc < MAX_SLOTS) { g_map[t][s] = (short)sc; g_S[t][sc] = s; sc++; }
    }
    g_scnt[t] = sc;
}

// ---------------- K3: find all edges into the frontier set ----------------
__global__ void k_pass2(const int* __restrict__ ei) {
    __shared__ short smap[NN];        // 32 KB
    int t = blockIdx.y;
    { // stage the map row in shared
        const int* gm = (const int*)g_map[t];
        int* sm = (int*)smap;
        for (int i = threadIdx.x; i < NN / 2; i += blockDim.x) sm[i] = gm[i];
    }
    __syncthreads();
    const int* src = ei + (size_t)t * 2 * NE;
    const int* dst = src + NE;
    int per_block = NE / gridDim.x;
    int e0 = blockIdx.x * per_block;
    for (int e = e0 + threadIdx.x * 4; e < e0 + per_block; e += blockDim.x * 4) {
        int4 d = *(const int4*)(dst + e);
        int dd[4] = { d.x, d.y, d.z, d.w };
        #pragma unroll
        for (int k = 0; k < 4; k++) {
            int sl = smap[dd[k]];
            if (sl >= 0) {
                int p = atomicAdd(&g_incnt[t], 1);
                if (p < CAPE) {
                    g_ie_e[t][p] = e + k; g_ie_src[t][p] = src[e + k]; g_ie_slot[t][p] = sl;
                }
            }
        }
    }
}

// ---------------- K4: GAT layer 1 at frontier nodes; emit xl2 scalars ----------------
__global__ void k_gat1(const float* __restrict__ x, const float* __restrict__ Wl1,
                       const float* __restrict__ attl1, const float* __restrict__ attr1,
                       const float* __restrict__ b1, const float* __restrict__ Wl2) {
    int t = blockIdx.y;
    int slot = blockIdx.x;
    if (slot >= g_scnt[t]) return;

    __shared__ float sWl[F_IN * HID];
    __shared__ float sAl[HID], sAr[HID], sB[HID], sW2[HID];
    __shared__ int   se[LOCAL_CAP], ss[LOCAL_CAP];
    __shared__ float sal[LOCAL_CAP][H1];
    __shared__ float sm_[H1], sden[H1], sarU[H1];
    __shared__ float sfmul[LOCAL_CAP], sfadd[LOCAL_CAP];
    __shared__ float sred[HID];
    __shared__ int   sdeg;

    int tid = threadIdx.x;              // 192 threads
    int u = g_S[t][slot];
    int h = tid >> 4, c = tid & 15;

    for (int i = tid; i < F_IN * HID; i += HID) sWl[i] = Wl1[i];
    sAl[tid] = attl1[tid]; sAr[tid] = attr1[tid]; sB[tid] = b1[tid]; sW2[tid] = Wl2[tid];
    if (tid == 0) sdeg = 0;
    __syncthreads();

    int cnt = g_incnt[t]; if (cnt > CAPE) cnt = CAPE;
    for (int i = tid; i < cnt; i += HID) {
        if (g_ie_slot[t][i] == slot) {
            int p = atomicAdd(&sdeg, 1);
            if (p < LOCAL_CAP - 1) { se[p] = g_ie_e[t][i]; ss[p] = g_ie_src[t][i]; }
        }
    }
    __syncthreads();
    int deg = sdeg; if (deg > LOCAL_CAP - 1) deg = LOCAL_CAP - 1;
    if (tid == 0) {
        for (int i = 1; i < deg; i++) {                     // canonical order
            int ke = se[i], ks = ss[i], j = i - 1;
            while (j >= 0 && se[j] > ke) { se[j + 1] = se[j]; ss[j + 1] = ss[j]; j--; }
            se[j + 1] = ke; ss[j + 1] = ks;
        }
        se[deg] = 0x7fffffff; ss[deg] = u;                  // self-loop last (never edited)
    }
    __syncthreads();
    int ndeg = deg + 1;

    // ar_u from xl1[u]
    {
        const float* xp = x + ((size_t)t * NN + u) * F_IN;
        float v = 0.f;
        #pragma unroll
        for (int k = 0; k < F_IN; k++) v += xp[k] * sWl[k * HID + tid];
        float r = v * sAr[tid];
        #pragma unroll
        for (int off = 8; off; off >>= 1) r += __shfl_xor_sync(0xffffffffu, r, off, 16);
        if (c == 0) sarU[h] = r;
    }

    // phase 1: per-edge attention logits (al)
    for (int i = 0; i < ndeg; i++) {
        const float* xp = x + ((size_t)t * NN + ss[i]) * F_IN;
        float v = 0.f;
        #pragma unroll
        for (int k = 0; k < F_IN; k++) v += xp[k] * sWl[k * HID + tid];
        float a = v * sAl[tid];
        #pragma unroll
        for (int off = 8; off; off >>= 1) a += __shfl_xor_sync(0xffffffffu, a, off, 16);
        if (c == 0) sal[i][h] = a;
    }
    __syncthreads();

    // softmax params per head + per-edge edit factors
    if (tid < H1) {
        int hh = tid;
        float m = -1e30f;
        for (int i = 0; i < ndeg; i++) { float a = lrelu(sal[i][hh] + sarU[hh]); if (a > m) m = a; }
        float den = 0.f;
        for (int i = 0; i < ndeg; i++) den += expf(lrelu(sal[i][hh] + sarU[hh]) - m);
        sm_[hh] = m; sden[hh] = den + 1e-16f;
    }
    if (tid >= 32 && tid < 32 + ndeg) {
        int i = tid - 32; float mu, ad; edit_factor(se[i], mu, ad); sfmul[i] = mu; sfadd[i] = ad;
    }
    __syncthreads();

    // phase 2: weighted aggregation (recompute xl1)
    float acc = 0.f;
    for (int i = 0; i < ndeg; i++) {
        float a = lrelu(sal[i][h] + sarU[h]);
        float alpha = expf(a - sm_[h]) / sden[h];
        alpha = sfmul[i] * alpha + sfadd[i];
        const float* xp = x + ((size_t)t * NN + ss[i]) * F_IN;
        float v = 0.f;
        #pragma unroll
        for (int k = 0; k < F_IN; k++) v += xp[k] * sWl[k * HID + tid];
        acc += alpha * v;
    }
    acc += sB[tid];
    float e1 = acc > 0.f ? acc : (expf(acc) - 1.f);          // ELU
    // layer-2 linear: xl2[u] = sum_j elu(h1)_j * Wl2[j]
    sred[tid] = e1 * sW2[tid];
    __syncthreads();
    if (tid < 64) sred[tid] = sred[tid] + sred[tid + 64] + sred[tid + 128];
    __syncthreads();
    if (tid < 32) {
        float v = sred[tid] + sred[tid + 32];
        #pragma unroll
        for (int off = 16; off; off >>= 1) v += __shfl_xor_sync(0xffffffffu, v, off);
        if (tid == 0) g_xl2[t][slot] = v;
    }
}

// ---------------- K5: GAT layer 2 at node 0 -> series[t] ----------------
__global__ void k_layer2(const float* __restrict__ attl2, const float* __restrict__ attr2,
                         const float* __restrict__ b2) {
    __shared__ float sxs[CAP0 + 1], sa[CAP0 + 1];
    int t = blockIdx.x;
    if (threadIdx.x != 0) return;
    int n = g_cnt0[t];
    float al2 = attl2[0], ar2v = attr2[0];
    float x0 = g_xl2[t][0];
    float ar0 = x0 * ar2v;
    float m = -1e30f;
    for (int i = 0; i <= n; i++) {
        float xs = (i < n) ? g_xl2[t][g_map[t][g_s0[t][i]]] : x0;
        float a = lrelu(xs * al2 + ar0);
        sxs[i] = xs; sa[i] = a;
        if (a > m) m = a;
    }
    float den = 0.f;
    for (int i = 0; i <= n; i++) den += expf(sa[i] - m);
    den += 1e-16f;
    float outv = 0.f;
    for (int i = 0; i <= n; i++) {
        float alpha = expf(sa[i] - m) / den;
        int e = (i < n) ? g_e0[t][i] : 0x7fffffff;
        float mu, ad; edit_factor(e, mu, ad);
        outv += (mu * alpha + ad) * sxs[i];
    }
    g_series[t] = outv + b2[0];
}

// ---------------- K6: pack LSTM weights transposed as float4-over-k ----------------
__global__ void k_prep(const float* __restrict__ Whh0, const float* __restrict__ Wih1,
                       const float* __restrict__ Whh1) {
    int idx = blockIdx.x * blockDim.x + threadIdx.x;
    if (idx >= 32 * NG) return;
    int k4 = idx / NG, g = idx % NG;
    int b = g * 128 + 4 * k4;
    g_W0T[idx]  = make_float4(Whh0[b], Whh0[b + 1], Whh0[b + 2], Whh0[b + 3]);
    g_Wi1T[idx] = make_float4(Wih1[b], Wih1[b + 1], Wih1[b + 2], Wih1[b + 3]);
    g_Wh1T[idx] = make_float4(Whh1[b], Whh1[b + 1], Whh1[b + 2], Whh1[b + 3]);
}

__device__ __forceinline__ float sigm(float x) { return 1.f / (1.f + expf(-x)); }

// ---------------- K7: 2-layer LSTM, one block per batch window ----------------
__global__ __launch_bounds__(NG, 1)
void k_lstm(const float* __restrict__ Wih0, const float* __restrict__ bih0,
            const float* __restrict__ bhh0, const float* __restrict__ bih1,
            const float* __restrict__ bhh1, const float* __restrict__ Wlin,
            const float* __restrict__ blin, float* __restrict__ out) {
    __shared__ __align__(16) float sh0[128];
    __shared__ __align__(16) float sh1[128];
    __shared__ float sg[NG];
    __shared__ float sx[32];
    int b = blockIdx.x, g = threadIdx.x;
    if (g < 32) sx[g] = g_series[b + g];
    if (g < 128) { sh0[g] = 0.f; sh1[g] = 0.f; }
    float c0 = 0.f, c1 = 0.f;
    float wih0 = Wih0[g];
    float bA = bih0[g] + bhh0[g];
    float bB = bih1[g] + bhh1[g];
    __syncthreads();
    const float4* h0q = (const float4*)sh0;
    const float4* h1q = (const float4*)sh1;

    for (int t = 0; t < 32; t++) {
        // layer 0 gate g
        float acc = wih0 * sx[t] + bA;
        #pragma unroll 8
        for (int k = 0; k < 32; k++) {
            float4 w = g_W0T[k * NG + g];
            float4 hh = h0q[k];
            acc += w.x * hh.x + w.y * hh.y + w.z * hh.z + w.w * hh.w;
        }
        sg[g] = acc;
        __syncthreads();
        if (g < 128) {
            float i_ = sigm(sg[g]);
            float f_ = sigm(sg[g + 128]);
            float g_ = tanhf(sg[g + 256]);
            float o_ = sigm(sg[g + 384]);
            c0 = f_ * c0 + i_ * g_;
            sh0[g] = o_ * tanhf(c0);
        }
        __syncthreads();
        // layer 1 gate g
        acc = bB;
        #pragma unroll 4
        for (int k = 0; k < 32; k++) {
            float4 wi = g_Wi1T[k * NG + g];
            float4 hh = h0q[k];
            acc += wi.x * hh.x + wi.y * hh.y + wi.z * hh.z + wi.w * hh.w;
            float4 wh = g_Wh1T[k * NG + g];
            float4 h1v = h1q[k];
            acc += wh.x * h1v.x + wh.y * h1v.y + wh.z * h1v.z + wh.w * h1v.w;
        }
        sg[g] = acc;
        __syncthreads();
        if (g < 128) {
            float i_ = sigm(sg[g]);
            float f_ = sigm(sg[g + 128]);
            float g_ = tanhf(sg[g + 256]);
            float o_ = sigm(sg[g + 384]);
            c1 = f_ * c1 + i_ * g_;
            sh1[g] = o_ * tanhf(c1);
        }
        __syncthreads();
    }

    float p = (g < 128) ? sh1[g] * Wlin[g] : 0.f;
    sg[g] = p;
    __syncthreads();
    if (g < 256) sg[g] += sg[g + 256];
    __syncthreads();
    if (g < 128) sg[g] += sg[g + 128];
    __syncthreads();
    if (g < 32) {
        float v = sg[g] + sg[g + 32] + sg[g + 64] + sg[g + 96];
        #pragma unroll
        for (int off = 16; off; off >>= 1) v += __shfl_xor_sync(0xffffffffu, v, off);
        if (g == 0) out[b] = v + blin[0];
    }
}

// ---------------- launch ----------------
extern "C" void kernel_launch(void* const* d_in, const int* in_sizes, int n_in,
                              void* d_out, int out_size) {
    const float* x     = (const float*)d_in[0];
    const int*   ei    = (const int*)d_in[1];
    const float* Wl1   = (const float*)d_in[2];
    const float* attl1 = (const float*)d_in[3];
    const float* attr1 = (const float*)d_in[4];
    const float* b1    = (const float*)d_in[5];
    const float* Wl2   = (const float*)d_in[6];
    const float* attl2 = (const float*)d_in[7];
    const float* attr2 = (const float*)d_in[8];
    const float* b2    = (const float*)d_in[9];
    const float* Wih0  = (const float*)d_in[10];
    const float* Whh0  = (const float*)d_in[11];
    const float* bih0  = (const float*)d_in[12];
    const float* bhh0  = (const float*)d_in[13];
    const float* Wih1  = (const float*)d_in[14];
    const float* Whh1  = (const float*)d_in[15];
    const float* bih1  = (const float*)d_in[16];
    const float* bhh1  = (const float*)d_in[17];
    const float* Wlin  = (const float*)d_in[18];
    const float* blin  = (const float*)d_in[19];
    float* out = (float*)d_out;

    k_init<<<256, 256>>>();
    k_pass1<<<dim3(32, T_STEPS), 256>>>(ei);
    k_build<<<T_STEPS, 32>>>();
    k_pass2<<<dim3(32, T_STEPS), 256>>>(ei);
    k_gat1<<<dim3(MAX_SLOTS, T_STEPS), HID>>>(x, Wl1, attl1, attr1, b1, Wl2);
    k_layer2<<<T_STEPS, 32>>>(attl2, attr2, b2);
    k_prep<<<64, 256>>>(Whh0, Wih1, Whh1);
    k_lstm<<<NB, NG>>>(Wih0, bih0, bhh0, bih1, bhh1, Wlin, blin, out);
}

// round 2
// speedup vs baseline: 1.5445x; 1.5445x over previous
#include <cuda_runtime.h>
#include <math.h>
#include <stdint.h>

#define T_STEPS 64
#define NN 16384
#define NE 262144
#define F_IN 8
#define H1 12
#define C1 16
#define HID 192
#define CAP0 256
#define MAX_SLOTS 128
#define CAPE 4096
#define LOCAL_CAP 128

// ---------------- scratch (static device globals; no allocation) ----------------
__device__ int   g_cnt0[T_STEPS];
__device__ int   g_e0[T_STEPS][CAP0];
__device__ int   g_s0[T_STEPS][CAP0];
__device__ int   g_scnt[T_STEPS];
__device__ int   g_S[T_STEPS][MAX_SLOTS];
__device__ short g_map[T_STEPS][NN];
__device__ int   g_incnt[T_STEPS];
__device__ int   g_ie_e[T_STEPS][CAPE];
__device__ int   g_ie_src[T_STEPS][CAPE];
__device__ int   g_ie_dst[T_STEPS][CAPE];
__device__ float g_xl2[T_STEPS][MAX_SLOTS];
__device__ float g_series[T_STEPS];

__device__ __forceinline__ float lrelu(float x) { return x > 0.f ? x : 0.2f * x; }
__device__ __forceinline__ float sigm(float x) { return 1.f / (1.f + expf(-x)); }
__device__ __forceinline__ float dot4(float4 a, float4 b) {
    return a.x * b.x + a.y * b.y + a.z * b.z + a.w * b.w;
}

__device__ __forceinline__ void edit_factor(int e, float& mul, float& add) {
    mul = 1.f; add = 0.f;
    if (e >= 0 && e < 23) {
        switch (e) {
            case 1: case 2: case 12: case 17: case 19: case 22: mul = 0.9f; break;
            case 7: case 14: mul = 0.9f; add = 0.1f; break;
            case 10: case 13: mul = 0.9f; add = 0.05f; break;
            default: break;
        }
    }
}

// ---------------- K0: init counters + node->slot map ----------------
__global__ void k_init() {
    int idx = blockIdx.x * blockDim.x + threadIdx.x;
    int stride = gridDim.x * blockDim.x;
    int* mp = (int*)g_map;
    const int nwords = T_STEPS * NN / 2;
    for (int i = idx; i < nwords; i += stride) mp[i] = -1;  // two -1 shorts
    if (idx < T_STEPS) { g_cnt0[idx] = 0; g_scnt[idx] = 0; g_incnt[idx] = 0; }
}

// ---------------- K1: find edges with dst == 0 (4x int4 unrolled) ----------------
__global__ void k_pass1(const int* __restrict__ ei) {
    const int t = blockIdx.y;
    const int* __restrict__ src = ei + (size_t)t * 2 * NE;
    const int* __restrict__ dst = src + NE;
    const int per_block = NE / 32;
    const int e0 = blockIdx.x * per_block;
    for (int e = e0 + threadIdx.x * 16; e < e0 + per_block; e += 256 * 16) {
        int4 v0 = *(const int4*)(dst + e);
        int4 v1 = *(const int4*)(dst + e + 4);
        int4 v2 = *(const int4*)(dst + e + 8);
        int4 v3 = *(const int4*)(dst + e + 12);
        int vals[16] = { v0.x, v0.y, v0.z, v0.w, v1.x, v1.y, v1.z, v1.w,
                         v2.x, v2.y, v2.z, v2.w, v3.x, v3.y, v3.z, v3.w };
        #pragma unroll
        for (int k = 0; k < 16; k++) {
            if (vals[k] == 0) {
                int p = atomicAdd(&g_cnt0[t], 1);
                if (p < CAP0) { g_e0[t][p] = e + k; g_s0[t][p] = src[e + k]; }
            }
        }
    }
}

// ---------------- K2: sort node-0 edges, build frontier set S + map ----------------
__global__ void k_build() {
    int t = blockIdx.x;
    if (threadIdx.x != 0) return;
    int n = g_cnt0[t]; if (n > CAP0) n = CAP0;
    g_cnt0[t] = n;
    for (int i = 1; i < n; i++) {  // canonical order -> deterministic sums
        int ke = g_e0[t][i], ks = g_s0[t][i], j = i - 1;
        while (j >= 0 && g_e0[t][j] > ke) {
            g_e0[t][j + 1] = g_e0[t][j]; g_s0[t][j + 1] = g_s0[t][j]; j--;
        }
        g_e0[t][j + 1] = ke; g_s0[t][j + 1] = ks;
    }
    int sc = 0;
    g_map[t][0] = 0; g_S[t][0] = 0; sc = 1;   // node 0 = slot 0
    for (int i = 0; i < n; i++) {
        int s = g_s0[t][i];
        if (g_map[t][s] < 0 && sc < MAX_SLOTS) { g_map[t][s] = (short)sc; g_S[t][sc] = s; sc++; }
    }
    g_scnt[t] = sc;
}

// ---------------- K3: find all edges into the frontier set (2KB bitmap) ----------------
__global__ void k_pass2(const int* __restrict__ ei) {
    __shared__ unsigned bm[NN / 32];   // 2 KB membership bitmap
    const int t = blockIdx.y;
    for (int i = threadIdx.x; i < NN / 32; i += 256) bm[i] = 0;
    __syncthreads();
    if (threadIdx.x < g_scnt[t]) {
        int node = g_S[t][threadIdx.x];
        atomicOr(&bm[node >> 5], 1u << (node & 31));
    }
    __syncthreads();
    const int* __restrict__ src = ei + (size_t)t * 2 * NE;
    const int* __restrict__ dst = src + NE;
    const int per_block = NE / 32;
    const int e0 = blockIdx.x * per_block;
    for (int e = e0 + threadIdx.x * 16; e < e0 + per_block; e += 256 * 16) {
        int4 v0 = *(const int4*)(dst + e);
        int4 v1 = *(const int4*)(dst + e + 4);
        int4 v2 = *(const int4*)(dst + e + 8);
        int4 v3 = *(const int4*)(dst + e + 12);
        int vals[16] = { v0.x, v0.y, v0.z, v0.w, v1.x, v1.y, v1.z, v1.w,
                         v2.x, v2.y, v2.z, v2.w, v3.x, v3.y, v3.z, v3.w };
        #pragma unroll
        for (int k = 0; k < 16; k++) {
            int d = vals[k];
            if ((bm[d >> 5] >> (d & 31)) & 1u) {
                int p = atomicAdd(&g_incnt[t], 1);
                if (p < CAPE) { g_ie_e[t][p] = e + k; g_ie_src[t][p] = src[e + k]; g_ie_dst[t][p] = d; }
            }
        }
    }
}

// ---------------- K4: GAT layer 1 at frontier nodes; emit xl2 scalars ----------------
__global__ void k_gat1(const float* __restrict__ x, const float* __restrict__ Wl1,
                       const float* __restrict__ attl1, const float* __restrict__ attr1,
                       const float* __restrict__ b1, const float* __restrict__ Wl2) {
    int t = blockIdx.y;
    int slot = blockIdx.x;
    if (slot >= g_scnt[t]) return;

    __shared__ float sWl[F_IN * HID];
    __shared__ float sAl[HID], sAr[HID], sB[HID], sW2[HID];
    __shared__ int   se[LOCAL_CAP], ss[LOCAL_CAP];
    __shared__ float sxr[LOCAL_CAP][F_IN];
    __shared__ float sal[LOCAL_CAP][H1];
    __shared__ float sm_[H1], sden[H1], sarU[H1];
    __shared__ float sfmul[LOCAL_CAP], sfadd[LOCAL_CAP];
    __shared__ float sred[HID];
    __shared__ int   sdeg;

    int tid = threadIdx.x;              // 192 threads
    int u = g_S[t][slot];
    int h = tid >> 4, c = tid & 15;

    for (int i = tid; i < F_IN * HID; i += HID) sWl[i] = Wl1[i];
    sAl[tid] = attl1[tid]; sAr[tid] = attr1[tid]; sB[tid] = b1[tid]; sW2[tid] = Wl2[tid];
    if (tid == 0) sdeg = 0;
    __syncthreads();

    int cnt = g_incnt[t]; if (cnt > CAPE) cnt = CAPE;
    for (int i = tid; i < cnt; i += HID) {
        if (g_ie_dst[t][i] == u) {
            int p = atomicAdd(&sdeg, 1);
            if (p < LOCAL_CAP - 1) { se[p] = g_ie_e[t][i]; ss[p] = g_ie_src[t][i]; }
        }
    }
    __syncthreads();
    int deg = sdeg; if (deg > LOCAL_CAP - 1) deg = LOCAL_CAP - 1;
    if (tid == 0) {
        for (int i = 1; i < deg; i++) {                     // canonical order
            int ke = se[i], ks = ss[i], j = i - 1;
            while (j >= 0 && se[j] > ke) { se[j + 1] = se[j]; ss[j + 1] = ss[j]; j--; }
            se[j + 1] = ke; ss[j + 1] = ks;
        }
        se[deg] = 0x7fffffff; ss[deg] = u;                  // self-loop last (never edited)
    }
    __syncthreads();
    int ndeg = deg + 1;

    // stage all needed x rows into shared (one latency instead of ndeg serial)
    for (int i = tid; i < ndeg * F_IN; i += HID)
        sxr[i >> 3][i & 7] = x[((size_t)t * NN + ss[i >> 3]) * F_IN + (i & 7)];
    __syncthreads();

    // ar_u from xl1[u] (self row is at index deg)
    {
        float v = 0.f;
        #pragma unroll
        for (int k = 0; k < F_IN; k++) v += sxr[deg][k] * sWl[k * HID + tid];
        float r = v * sAr[tid];
        #pragma unroll
        for (int off = 8; off; off >>= 1) r += __shfl_xor_sync(0xffffffffu, r, off, 16);
        if (c == 0) sarU[h] = r;
    }

    // phase 1: per-edge attention logits (al)
    for (int i = 0; i < ndeg; i++) {
        float v = 0.f;
        #pragma unroll
        for (int k = 0; k < F_IN; k++) v += sxr[i][k] * sWl[k * HID + tid];
        float a = v * sAl[tid];
        #pragma unroll
        for (int off = 8; off; off >>= 1) a += __shfl_xor_sync(0xffffffffu, a, off, 16);
        if (c == 0) sal[i][h] = a;
    }
    __syncthreads();

    // softmax params per head + per-edge edit factors
    if (tid < H1) {
        int hh = tid;
        float m = -1e30f;
        for (int i = 0; i < ndeg; i++) { float a = lrelu(sal[i][hh] + sarU[hh]); if (a > m) m = a; }
        float den = 0.f;
        for (int i = 0; i < ndeg; i++) den += expf(lrelu(sal[i][hh] + sarU[hh]) - m);
        sm_[hh] = m; sden[hh] = den + 1e-16f;
    }
    if (tid >= 32 && tid < 32 + ndeg) {
        int i = tid - 32; float mu, ad; edit_factor(se[i], mu, ad); sfmul[i] = mu; sfadd[i] = ad;
    }
    __syncthreads();

    // phase 2: weighted aggregation
    float acc = 0.f;
    for (int i = 0; i < ndeg; i++) {
        float a = lrelu(sal[i][h] + sarU[h]);
        float alpha = expf(a - sm_[h]) / sden[h];
        alpha = sfmul[i] * alpha + sfadd[i];
        float v = 0.f;
        #pragma unroll
        for (int k = 0; k < F_IN; k++) v += sxr[i][k] * sWl[k * HID + tid];
        acc += alpha * v;
    }
    acc += sB[tid];
    float e1 = acc > 0.f ? acc : (expf(acc) - 1.f);          // ELU
    sred[tid] = e1 * sW2[tid];
    __syncthreads();
    if (tid < 64) sred[tid] = sred[tid] + sred[tid + 64] + sred[tid + 128];
    __syncthreads();
    if (tid < 32) {
        float v = sred[tid] + sred[tid + 32];
        #pragma unroll
        for (int off = 16; off; off >>= 1) v += __shfl_xor_sync(0xffffffffu, v, off);
        if (tid == 0) g_xl2[t][slot] = v;
    }
}

// ---------------- K5: GAT layer 2 at node 0 -> series[t] ----------------
__global__ void k_layer2(const float* __restrict__ attl2, const float* __restrict__ attr2,
                         const float* __restrict__ b2) {
    __shared__ float sxs[CAP0 + 1], sa[CAP0 + 1];
    int t = blockIdx.x;
    if (threadIdx.x != 0) return;
    int n = g_cnt0[t];
    float al2 = attl2[0], ar2v = attr2[0];
    float x0 = g_xl2[t][0];
    float ar0 = x0 * ar2v;
    float m = -1e30f;
    for (int i = 0; i <= n; i++) {
        float xs = (i < n) ? g_xl2[t][g_map[t][g_s0[t][i]]] : x0;
        float a = lrelu(xs * al2 + ar0);
        sxs[i] = xs; sa[i] = a;
        if (a > m) m = a;
    }
    float den = 0.f;
    for (int i = 0; i <= n; i++) den += expf(sa[i] - m);
    den += 1e-16f;
    float outv = 0.f;
    for (int i = 0; i <= n; i++) {
        float alpha = expf(sa[i] - m) / den;
        int e = (i < n) ? g_e0[t][i] : 0x7fffffff;
        float mu, ad; edit_factor(e, mu, ad);
        outv += (mu * alpha + ad) * sxs[i];
    }
    g_series[t] = outv + b2[0];
}

// ================= K6: cluster-4 LSTM, weights resident, DSMEM h-exchange =================
#define WCPITCH 17

struct __align__(16) LSmem {
    float4 wc[512 * WCPITCH];   // layer-1 per-thread weight chunks (conflict-free pitch)
    float4 h0p[2][36];          // padded h0 double-buffer (k4 -> k4 + k4/8)
    float4 h1p[2][36];
    float xs[32];
    float bA[128];
    float bB[128];
    float wih0s[128];
    float sg[128];
};

__device__ __forceinline__ int hpad(int k4) { return k4 + (k4 >> 3); }

__device__ __forceinline__ unsigned cl_rank() {
    unsigned r; asm("mov.u32 %0, %%cluster_ctarank;" : "=r"(r)); return r;
}
__device__ __forceinline__ void cl_sync() {
    asm volatile("barrier.cluster.arrive.aligned;\n\tbarrier.cluster.wait.aligned;" ::: "memory");
}
__device__ __forceinline__ void cl_store_f32(float* p, unsigned rank, float v) {
    uint32_t a = (uint32_t)__cvta_generic_to_shared(p);
    uint32_t pa;
    asm("mapa.shared::cluster.u32 %0, %1, %2;" : "=r"(pa) : "r"(a), "r"(rank));
    asm volatile("st.shared::cluster.f32 [%0], %1;" :: "r"(pa), "f"(v) : "memory");
}

__global__ void __cluster_dims__(4, 1, 1) __launch_bounds__(512, 1)
k_lstm_cl(const float* __restrict__ Wih0, const float* __restrict__ Whh0,
          const float* __restrict__ bih0, const float* __restrict__ bhh0,
          const float* __restrict__ Wih1, const float* __restrict__ Whh1,
          const float* __restrict__ bih1, const float* __restrict__ bhh1,
          const float* __restrict__ Wlin, const float* __restrict__ blin,
          float* __restrict__ out) {
    extern __shared__ __align__(16) char smraw[];
    LSmem* sm = (LSmem*)smraw;
    const unsigned rank = cl_rank();
    const int batch = blockIdx.x >> 2;
    const int tid = threadIdx.x;
    const int lr = tid >> 2, q = tid & 3;     // local row 0..127, k-quarter 0..3
    const int gt = lr >> 5, dl = lr & 31;     // gate type, local dim
    const int gr = gt * 128 + (int)rank * 32 + dl;  // global gate row

    // layer-0 weights -> registers (8 float4 = this thread's k-quarter of Whh0 row)
    float4 w0r[8];
    {
        const float4* W0 = (const float4*)(Whh0 + (size_t)gr * 128);
        #pragma unroll
        for (int j = 0; j < 8; j++) w0r[j] = W0[8 * q + j];
    }
    // layer-1 weight chunk -> smem (16 float4, pitched)
    {
        const float* Wsrc = (q < 2) ? Wih1 : Whh1;
        const float4* W1 = (const float4*)(Wsrc + (size_t)gr * 128);
        #pragma unroll
        for (int j = 0; j < 16; j++) sm->wc[tid * WCPITCH + j] = W1[16 * (q & 1) + j];
    }
    if (q == 0) {
        sm->wih0s[lr] = Wih0[gr];
        sm->bA[lr] = bih0[gr] + bhh0[gr];
        sm->bB[lr] = bih1[gr] + bhh1[gr];
    }
    if (tid < 32) sm->xs[tid] = g_series[batch + tid];
    {   // zero padded h buffers (4 * 144 floats)
        float* hz = (float*)&sm->h0p[0][0];
        for (int i = tid; i < 4 * 144; i += 512) hz[i] = 0.f;
    }
    float c0 = 0.f, c1 = 0.f;                 // cell state lives in updater threads (tid<32)
    cl_sync();

    int fin = 0;
    for (int t = 0; t < 32; t++) {
        const int pb = t & 1, nb = pb ^ 1;

        // ---- layer 0: gate slice matvec over h0[pb] ----
        {
            const float4* hv = sm->h0p[pb];
            float a1 = 0.f, a2 = 0.f;
            #pragma unroll
            for (int j = 0; j < 8; j += 2) {
                a1 += dot4(w0r[j],     hv[hpad(8 * q + j)]);
                a2 += dot4(w0r[j + 1], hv[hpad(8 * q + j + 1)]);
            }
            float acc = a1 + a2;
            acc += __shfl_xor_sync(0xffffffffu, acc, 1, 4);
            acc += __shfl_xor_sync(0xffffffffu, acc, 2, 4);
            if (q == 0) sm->sg[lr] = acc + sm->bA[lr] + sm->wih0s[lr] * sm->xs[t];
        }
        __syncthreads();
        if (tid < 32) {
            float gi = sigm(sm->sg[tid]);
            float gf = sigm(sm->sg[32 + tid]);
            float gg = tanhf(sm->sg[64 + tid]);
            float go = sigm(sm->sg[96 + tid]);
            c0 = gf * c0 + gi * gg;
            float hval = go * tanhf(c0);
            int d = (int)rank * 32 + tid;
            int fi = hpad(d >> 2) * 4 + (d & 3);
            float* lp = ((float*)sm->h0p[nb]) + fi;
            #pragma unroll
            for (unsigned r = 0; r < 4; r++) cl_store_f32(lp, r, hval);
        }
        cl_sync();

        // ---- layer 1: gate slice matvec over [h0[nb]; h1[pb]] ----
        {
            const float4* hsrc = (q < 2) ? sm->h0p[nb] : sm->h1p[pb];
            const float4* wrow = &sm->wc[tid * WCPITCH];
            const int hb = 16 * (q & 1);
            float a1 = 0.f, a2 = 0.f;
            #pragma unroll
            for (int j = 0; j < 16; j += 2) {
                a1 += dot4(wrow[j],     hsrc[hpad(hb + j)]);
                a2 += dot4(wrow[j + 1], hsrc[hpad(hb + j + 1)]);
            }
            float acc = a1 + a2;
            acc += __shfl_xor_sync(0xffffffffu, acc, 1, 4);
            acc += __shfl_xor_sync(0xffffffffu, acc, 2, 4);
            if (q == 0) sm->sg[lr] = acc + sm->bB[lr];
        }
        __syncthreads();
        if (tid < 32) {
            float gi = sigm(sm->sg[tid]);
            float gf = sigm(sm->sg[32 + tid]);
            float gg = tanhf(sm->sg[64 + tid]);
            float go = sigm(sm->sg[96 + tid]);
            c1 = gf * c1 + gi * gg;
            float hval = go * tanhf(c1);
            int d = (int)rank * 32 + tid;
            int fi = hpad(d >> 2) * 4 + (d & 3);
            float* lp = ((float*)sm->h1p[nb]) + fi;
            #pragma unroll
            for (unsigned r = 0; r < 4; r++) cl_store_f32(lp, r, hval);
        }
        cl_sync();
        fin = nb;
    }

    // ---- final projection (rank 0 only; every CTA has the full h1) ----
    if (rank == 0) {
        float v = 0.f;
        if (tid < 128) {
            int fi = hpad(tid >> 2) * 4 + (tid & 3);
            v = ((float*)sm->h1p[fin])[fi] * Wlin[tid];
        }
        if (tid < 128) sm->sg[tid] = v;
        __syncthreads();
        if (tid < 32) {
            float s = sm->sg[tid] + sm->sg[tid + 32] + sm->sg[tid + 64] + sm->sg[tid + 96];
            #pragma unroll
            for (int off = 16; off; off >>= 1) s += __shfl_xor_sync(0xffffffffu, s, off);
            if (tid == 0) out[batch] = s + blin[0];
        }
    }
}

// ---------------- launch ----------------
extern "C" void kernel_launch(void* const* d_in, const int* in_sizes, int n_in,
                              void* d_out, int out_size) {
    const float* x     = (const float*)d_in[0];
    const int*   ei    = (const int*)d_in[1];
    const float* Wl1   = (const float*)d_in[2];
    const float* attl1 = (const float*)d_in[3];
    const float* attr1 = (const float*)d_in[4];
    const float* b1    = (const float*)d_in[5];
    const float* Wl2   = (const float*)d_in[6];
    const float* attl2 = (const float*)d_in[7];
    const float* attr2 = (const float*)d_in[8];
    const float* b2    = (const float*)d_in[9];
    const float* Wih0  = (const float*)d_in[10];
    const float* Whh0  = (const float*)d_in[11];
    const float* bih0  = (const float*)d_in[12];
    const float* bhh0  = (const float*)d_in[13];
    const float* Wih1  = (const float*)d_in[14];
    const float* Whh1  = (const float*)d_in[15];
    const float* bih1  = (const float*)d_in[16];
    const float* bhh1  = (const float*)d_in[17];
    const float* Wlin  = (const float*)d_in[18];
    const float* blin  = (const float*)d_in[19];
    float* out = (float*)d_out;

    static int smem_set = 0;
    if (!smem_set) {
        cudaFuncSetAttribute(k_lstm_cl, cudaFuncAttributeMaxDynamicSharedMemorySize,
                             (int)sizeof(LSmem));
        smem_set = 1;
    }

    k_init<<<256, 256>>>();
    k_pass1<<<dim3(32, T_STEPS), 256>>>(ei);
    k_build<<<T_STEPS, 32>>>();
    k_pass2<<<dim3(32, T_STEPS), 256>>>(ei);
    k_gat1<<<dim3(MAX_SLOTS, T_STEPS), HID>>>(x, Wl1, attl1, attr1, b1, Wl2);
    k_layer2<<<T_STEPS, 32>>>(attl2, attr2, b2);
    k_lstm_cl<<<128, 512, sizeof(LSmem)>>>(Wih0, Whh0, bih0, bhh0,
                                           Wih1, Whh1, bih1, bhh1, Wlin, blin, out);
}